// round 1
// baseline (speedup 1.0000x reference)
#include <cuda_runtime.h>
#include <cuda_bf16.h>
#include <math.h>

// ---------------- problem constants ----------------
#define BB 4
#define SS 1024
#define LL 12
#define DD 768
#define HH 12
#define DKK 64
#define DFF 3072
#define VV 50257
#define NTOK (BB*SS)          // 4096

// ---------------- scratch (device globals; no allocs allowed) --------------
__device__ float g_x  [(size_t)NTOK * DD];
__device__ float g_h  [(size_t)NTOK * DD];
__device__ float g_q  [(size_t)NTOK * DD];
__device__ float g_k  [(size_t)NTOK * DD];
__device__ float g_v  [(size_t)NTOK * DD];
__device__ float g_tmp[(size_t)NTOK * DD];
__device__ float g_ff [(size_t)NTOK * DFF];
__device__ float g_att[(size_t)BB * HH * SS * SS];   // 201 MB

// ---------------- embedding: x = wte[idx] + wpe[s] ----------------
__global__ void embed_kernel(const int* __restrict__ idx,
                             const float* __restrict__ wte,
                             const float* __restrict__ wpe,
                             float* __restrict__ x)
{
    int row = blockIdx.x;              // 0..4095 = b*S+s
    int s   = row & (SS - 1);
    int tok = idx[row];
    int tid = threadIdx.x;             // 256
    #pragma unroll
    for (int l = 0; l < 3; l++) {
        int d = tid + l * 256;
        x[(size_t)row * DD + d] = wte[(size_t)tok * DD + d] + wpe[(size_t)s * DD + d];
    }
}

// ---------------- layernorm: one block per row (768) ----------------
__global__ void layernorm_kernel(const float* __restrict__ x,
                                 const float* __restrict__ w,
                                 const float* __restrict__ b,
                                 float* __restrict__ y)
{
    int row = blockIdx.x;
    const float* p = x + (size_t)row * DD;
    int tid = threadIdx.x;             // 256
    float v0 = p[tid], v1 = p[tid + 256], v2 = p[tid + 512];
    __shared__ float red[256];
    red[tid] = v0 + v1 + v2;
    __syncthreads();
    for (int st = 128; st > 0; st >>= 1) {
        if (tid < st) red[tid] += red[tid + st];
        __syncthreads();
    }
    float mean = red[0] * (1.0f / DD);
    __syncthreads();
    float d0 = v0 - mean, d1 = v1 - mean, d2 = v2 - mean;
    red[tid] = d0 * d0 + d1 * d1 + d2 * d2;
    __syncthreads();
    for (int st = 128; st > 0; st >>= 1) {
        if (tid < st) red[tid] += red[tid + st];
        __syncthreads();
    }
    float rstd = rsqrtf(red[0] * (1.0f / DD) + 1e-5f);
    float* q = y + (size_t)row * DD;
    q[tid]       = d0 * rstd * w[tid]       + b[tid];
    q[tid + 256] = d1 * rstd * w[tid + 256] + b[tid + 256];
    q[tid + 512] = d2 * rstd * w[tid + 512] + b[tid + 512];
}

// ---------------- generic fp32 GEMM: C = A[MxK] @ B[KxN] (+ epilogue) ------
// EPI: 0 none, 1 add Cin, 2 exact GELU
// BT : false -> B row-major [K,N]; true -> B row-major [N,K] (i.e. C=A@B^T)
// Requires: M % 128 == 0, K % 8 == 0. N arbitrary (guarded).
template<int EPI, bool BT>
__global__ __launch_bounds__(256)
void gemm_kernel(const float* __restrict__ A, const float* __restrict__ B,
                 const float* __restrict__ Cin, float* __restrict__ C,
                 int M, int N, int K)
{
    __shared__ float As[8][128];
    __shared__ float Bs[8][128];
    const int tid     = threadIdx.x;
    const int rowBase = blockIdx.y * 128;
    const int colBase = blockIdx.x * 128;

    const int arow = tid >> 1;
    const int akq  = (tid & 1) * 4;
    const int ty   = tid >> 4;       // 0..15
    const int tx   = tid & 15;       // 0..15

    float acc[8][8];
    #pragma unroll
    for (int i = 0; i < 8; i++)
        #pragma unroll
        for (int j = 0; j < 8; j++) acc[i][j] = 0.0f;

    for (int k0 = 0; k0 < K; k0 += 8) {
        // A tile: 128 rows x 8 k
        {
            float4 v = *(const float4*)(A + (size_t)(rowBase + arow) * K + k0 + akq);
            As[akq + 0][arow] = v.x;
            As[akq + 1][arow] = v.y;
            As[akq + 2][arow] = v.z;
            As[akq + 3][arow] = v.w;
        }
        if (!BT) {
            int brow  = tid >> 5;            // 0..7
            int bcol4 = (tid & 31) * 4;      // 0..124
            int col   = colBase + bcol4;
            if (colBase + 128 <= N) {
                *(float4*)&Bs[brow][bcol4] =
                    *(const float4*)(B + (size_t)(k0 + brow) * N + col);
            } else {
                float t[4];
                #pragma unroll
                for (int i = 0; i < 4; i++)
                    t[i] = (col + i < N) ? B[(size_t)(k0 + brow) * N + col + i] : 0.0f;
                Bs[brow][bcol4 + 0] = t[0];
                Bs[brow][bcol4 + 1] = t[1];
                Bs[brow][bcol4 + 2] = t[2];
                Bs[brow][bcol4 + 3] = t[3];
            }
        } else {
            int bn  = tid >> 1;
            int bkq = (tid & 1) * 4;
            int col = colBase + bn;
            float4 v = make_float4(0.f, 0.f, 0.f, 0.f);
            if (col < N)
                v = *(const float4*)(B + (size_t)col * K + k0 + bkq);
            Bs[bkq + 0][bn] = v.x;
            Bs[bkq + 1][bn] = v.y;
            Bs[bkq + 2][bn] = v.z;
            Bs[bkq + 3][bn] = v.w;
        }
        __syncthreads();

        #pragma unroll
        for (int kk = 0; kk < 8; kk++) {
            float a[8], b[8];
            *(float4*)&a[0] = *(const float4*)&As[kk][ty * 8];
            *(float4*)&a[4] = *(const float4*)&As[kk][ty * 8 + 4];
            *(float4*)&b[0] = *(const float4*)&Bs[kk][tx * 8];
            *(float4*)&b[4] = *(const float4*)&Bs[kk][tx * 8 + 4];
            #pragma unroll
            for (int i = 0; i < 8; i++)
                #pragma unroll
                for (int j = 0; j < 8; j++)
                    acc[i][j] = fmaf(a[i], b[j], acc[i][j]);
        }
        __syncthreads();
    }

    #pragma unroll
    for (int i = 0; i < 8; i++) {
        int row = rowBase + ty * 8 + i;
        #pragma unroll
        for (int j = 0; j < 8; j++) {
            int col = colBase + tx * 8 + j;
            if (col < N) {
                size_t o = (size_t)row * N + col;
                float v = acc[i][j];
                if (EPI == 1) v += Cin[o];
                if (EPI == 2) v = 0.5f * v * (1.0f + erff(v * 0.70710678118654752f));
                C[o] = v;
            }
        }
    }
}

// ---------------- attention scores: S[bh,i,j] = (q.k)/8, 0 if j>i -----------
__global__ __launch_bounds__(256)
void attn_scores_kernel(const float* __restrict__ Q, const float* __restrict__ Kt,
                        float* __restrict__ S_out)
{
    int it = blockIdx.x, jt = blockIdx.y, bh = blockIdx.z;
    if (jt > it) return;
    int b = bh / HH, h = bh % HH;
    int i0 = it * 64, j0 = jt * 64;

    __shared__ float qs[64][68];
    __shared__ float ks[64][68];
    int tid = threadIdx.x;
    #pragma unroll
    for (int l = 0; l < 4; l++) {
        int idx = tid + l * 256;         // 0..1023 float4 slots
        int r = idx >> 4, c4 = (idx & 15) * 4;
        *(float4*)&qs[r][c4] =
            *(const float4*)(Q + (size_t)(b * SS + i0 + r) * DD + h * DKK + c4);
        *(float4*)&ks[r][c4] =
            *(const float4*)(Kt + (size_t)(b * SS + j0 + r) * DD + h * DKK + c4);
    }
    __syncthreads();

    int ty = tid >> 4, tx = tid & 15;
    float acc[4][4] = {};
    #pragma unroll 8
    for (int k = 0; k < 64; k++) {
        float a[4], bb[4];
        #pragma unroll
        for (int ii = 0; ii < 4; ii++) a[ii] = qs[ty * 4 + ii][k];
        #pragma unroll
        for (int jj = 0; jj < 4; jj++) bb[jj] = ks[tx * 4 + jj][k];
        #pragma unroll
        for (int ii = 0; ii < 4; ii++)
            #pragma unroll
            for (int jj = 0; jj < 4; jj++)
                acc[ii][jj] = fmaf(a[ii], bb[jj], acc[ii][jj]);
    }

    const float inv_scale = 0.125f;      // 1/sqrt(DK)=1/8
    #pragma unroll
    for (int ii = 0; ii < 4; ii++) {
        int i = i0 + ty * 4 + ii;
        #pragma unroll
        for (int jj = 0; jj < 4; jj++) {
            int j = j0 + tx * 4 + jj;
            float v = (j <= i) ? acc[ii][jj] * inv_scale : 0.0f;
            S_out[((size_t)bh * SS + i) * SS + j] = v;
        }
    }
}

// ---------------- causal softmax, in place, one block per row --------------
__global__ void softmax_kernel(float* __restrict__ att)
{
    int row = blockIdx.x;               // bh*S + i
    int i   = row & (SS - 1);
    float* p = att + (size_t)row * SS;
    int n   = i + 1;
    int tid = threadIdx.x;              // 256

    __shared__ float red[256];
    float mx = -1e30f;
    for (int j = tid; j < n; j += 256) mx = fmaxf(mx, p[j]);
    red[tid] = mx; __syncthreads();
    for (int st = 128; st > 0; st >>= 1) {
        if (tid < st) red[tid] = fmaxf(red[tid], red[tid + st]);
        __syncthreads();
    }
    mx = red[0]; __syncthreads();

    float sum = 0.0f;
    for (int j = tid; j < n; j += 256) {
        float e = __expf(p[j] - mx);
        p[j] = e;
        sum += e;
    }
    red[tid] = sum; __syncthreads();
    for (int st = 128; st > 0; st >>= 1) {
        if (tid < st) red[tid] += red[tid + st];
        __syncthreads();
    }
    float inv = 1.0f / red[0];
    for (int j = tid; j < n; j += 256) p[j] *= inv;
}

// ---------------- O = att @ V  (per bh, 64-row tiles, K bounded by diag) ----
__global__ __launch_bounds__(256)
void attn_av_kernel(const float* __restrict__ att, const float* __restrict__ V,
                    float* __restrict__ O)
{
    int it = blockIdx.x, bh = blockIdx.y;
    int b = bh / HH, h = bh % HH;
    int i0 = it * 64;

    __shared__ float as_[64][68];
    __shared__ float vs [64][68];
    int tid = threadIdx.x;
    int ty = tid >> 4, tx = tid & 15;
    float acc[4][4] = {};

    const float* attBase = att + ((size_t)bh * SS + i0) * SS;
    int kmax = i0 + 64;                 // beyond this everything is masked 0

    for (int j0 = 0; j0 < kmax; j0 += 64) {
        #pragma unroll
        for (int l = 0; l < 4; l++) {
            int idx = tid + l * 256;
            int r = idx >> 4, c4 = (idx & 15) * 4;
            *(float4*)&as_[r][c4] = *(const float4*)(attBase + (size_t)r * SS + j0 + c4);
            *(float4*)&vs[r][c4] =
                *(const float4*)(V + (size_t)(b * SS + j0 + r) * DD + h * DKK + c4);
        }
        __syncthreads();
        #pragma unroll 8
        for (int k = 0; k < 64; k++) {
            float a[4], bb[4];
            #pragma unroll
            for (int ii = 0; ii < 4; ii++) a[ii] = as_[ty * 4 + ii][k];
            #pragma unroll
            for (int jj = 0; jj < 4; jj++) bb[jj] = vs[k][tx * 4 + jj];
            #pragma unroll
            for (int ii = 0; ii < 4; ii++)
                #pragma unroll
                for (int jj = 0; jj < 4; jj++)
                    acc[ii][jj] = fmaf(a[ii], bb[jj], acc[ii][jj]);
        }
        __syncthreads();
    }

    #pragma unroll
    for (int ii = 0; ii < 4; ii++) {
        int i = i0 + ty * 4 + ii;
        #pragma unroll
        for (int jj = 0; jj < 4; jj++) {
            int dk = tx * 4 + jj;
            O[(size_t)(b * SS + i) * DD + h * DKK + dk] = acc[ii][jj];
        }
    }
}

// ---------------- host launcher ----------------
extern "C" void kernel_launch(void* const* d_in, const int* in_sizes, int n_in,
                              void* d_out, int out_size)
{
    const int*   idx   = (const int*)  d_in[0];
    const float* wte   = (const float*)d_in[1];
    const float* wpe   = (const float*)d_in[2];
    const float* ln1_w = (const float*)d_in[3];
    const float* ln1_b = (const float*)d_in[4];
    const float* wq    = (const float*)d_in[5];
    const float* wk    = (const float*)d_in[6];
    const float* wv    = (const float*)d_in[7];
    const float* wo    = (const float*)d_in[8];
    const float* ln2_w = (const float*)d_in[9];
    const float* ln2_b = (const float*)d_in[10];
    const float* fc1   = (const float*)d_in[11];
    const float* fc2   = (const float*)d_in[12];
    const float* lnf_w = (const float*)d_in[13];
    const float* lnf_b = (const float*)d_in[14];
    float* out = (float*)d_out;

    float *x, *h, *q, *k, *v, *tmp, *ff, *att;
    cudaGetSymbolAddress((void**)&x,   g_x);
    cudaGetSymbolAddress((void**)&h,   g_h);
    cudaGetSymbolAddress((void**)&q,   g_q);
    cudaGetSymbolAddress((void**)&k,   g_k);
    cudaGetSymbolAddress((void**)&v,   g_v);
    cudaGetSymbolAddress((void**)&tmp, g_tmp);
    cudaGetSymbolAddress((void**)&ff,  g_ff);
    cudaGetSymbolAddress((void**)&att, g_att);

    embed_kernel<<<NTOK, 256>>>(idx, wte, wpe, x);

    dim3 gD(DD / 128, NTOK / 128);      // (6, 32)  for N=768
    dim3 gF(DFF / 128, NTOK / 128);     // (24, 32) for N=3072

    for (int l = 0; l < LL; l++) {
        const float* Wq = wq + (size_t)l * DD * DD;
        const float* Wk = wk + (size_t)l * DD * DD;
        const float* Wv = wv + (size_t)l * DD * DD;
        const float* Wo = wo + (size_t)l * DD * DD;
        const float* W1 = fc1 + (size_t)l * DD * DFF;
        const float* W2 = fc2 + (size_t)l * DFF * DD;

        layernorm_kernel<<<NTOK, 256>>>(x, ln1_w + l * DD, ln1_b + l * DD, h);

        gemm_kernel<0, false><<<gD, 256>>>(h, Wq, nullptr, q, NTOK, DD, DD);
        gemm_kernel<0, false><<<gD, 256>>>(h, Wk, nullptr, k, NTOK, DD, DD);
        gemm_kernel<0, false><<<gD, 256>>>(h, Wv, nullptr, v, NTOK, DD, DD);

        attn_scores_kernel<<<dim3(SS / 64, SS / 64, BB * HH), 256>>>(q, k, att);
        softmax_kernel<<<BB * HH * SS, 256>>>(att);
        attn_av_kernel<<<dim3(SS / 64, BB * HH), 256>>>(att, v, tmp);

        gemm_kernel<1, false><<<gD, 256>>>(tmp, Wo, x, x, NTOK, DD, DD);

        layernorm_kernel<<<NTOK, 256>>>(x, ln2_w + l * DD, ln2_b + l * DD, h);
        gemm_kernel<2, false><<<gF, 256>>>(h, W1, nullptr, ff, NTOK, DFF, DD);
        gemm_kernel<1, false><<<gD, 256>>>(ff, W2, x, x, NTOK, DD, DFF);
    }

    layernorm_kernel<<<NTOK, 256>>>(x, lnf_w, lnf_b, h);
    gemm_kernel<0, true><<<dim3((VV + 127) / 128, NTOK / 128), 256>>>(
        h, wte, nullptr, out, NTOK, VV, DD);
}

// round 2
// speedup vs baseline: 2.5514x; 2.5514x over previous
#include <cuda_runtime.h>
#include <cuda_bf16.h>
#include <math.h>

// ---------------- problem constants ----------------
#define BB 4
#define SS 1024
#define LL 12
#define DD 768
#define HH 12
#define DKK 64
#define DFF 3072
#define VV 50257
#define NTOK (BB*SS)          // 4096

// ---------------- scratch (device globals; no allocs allowed) --------------
__device__ float g_x  [(size_t)NTOK * DD];
__device__ float g_h  [(size_t)NTOK * DD];
__device__ float g_q  [(size_t)NTOK * DD];
__device__ float g_k  [(size_t)NTOK * DD];
__device__ float g_v  [(size_t)NTOK * DD];
__device__ float g_tmp[(size_t)NTOK * DD];
__device__ float g_ff [(size_t)NTOK * DFF];
__device__ float g_att[(size_t)BB * HH * SS * SS];   // 201 MB

// ---------------- embedding ----------------
__global__ void embed_kernel(const int* __restrict__ idx,
                             const float* __restrict__ wte,
                             const float* __restrict__ wpe,
                             float* __restrict__ x)
{
    int row = blockIdx.x;
    int s   = row & (SS - 1);
    int tok = idx[row];
    int tid = threadIdx.x;
    #pragma unroll
    for (int l = 0; l < 3; l++) {
        int d = tid + l * 256;
        x[(size_t)row * DD + d] = wte[(size_t)tok * DD + d] + wpe[(size_t)s * DD + d];
    }
}

// ---------------- layernorm ----------------
__global__ void layernorm_kernel(const float* __restrict__ x,
                                 const float* __restrict__ w,
                                 const float* __restrict__ b,
                                 float* __restrict__ y)
{
    int row = blockIdx.x;
    const float* p = x + (size_t)row * DD;
    int tid = threadIdx.x;
    float v0 = p[tid], v1 = p[tid + 256], v2 = p[tid + 512];
    __shared__ float red[256];
    red[tid] = v0 + v1 + v2;
    __syncthreads();
    for (int st = 128; st > 0; st >>= 1) {
        if (tid < st) red[tid] += red[tid + st];
        __syncthreads();
    }
    float mean = red[0] * (1.0f / DD);
    __syncthreads();
    float d0 = v0 - mean, d1 = v1 - mean, d2 = v2 - mean;
    red[tid] = d0 * d0 + d1 * d1 + d2 * d2;
    __syncthreads();
    for (int st = 128; st > 0; st >>= 1) {
        if (tid < st) red[tid] += red[tid + st];
        __syncthreads();
    }
    float rstd = rsqrtf(red[0] * (1.0f / DD) + 1e-5f);
    float* q = y + (size_t)row * DD;
    q[tid]       = d0 * rstd * w[tid]       + b[tid];
    q[tid + 256] = d1 * rstd * w[tid + 256] + b[tid + 256];
    q[tid + 512] = d2 * rstd * w[tid + 512] + b[tid + 512];
}

// ---------------- tf32 tensor-core GEMM ----------------
// C[4096 x N] = A[4096 x K] @ B   (+ epilogue)
// BT=false: B row-major [K,N].  BT=true: B row-major [N,K] (C = A @ B^T).
// EPI: 0 none, 1 add Cin, 2 exact GELU
// Block: 128x128 tile, 4 warps (2x2), warp tile 64x64, BK=16, double-buffered.
// grid.z selects among (B0,C0)/(B1,C1)/(B2,C2) for fused QKV.

__device__ __forceinline__ unsigned f2tf(float f) {
    unsigned u;
    asm("cvt.rna.tf32.f32 %0, %1;" : "=r"(u) : "f"(f));
    return u;
}

__device__ __forceinline__ void mma8(float* d, const unsigned* a, const unsigned* b) {
    asm volatile(
        "mma.sync.aligned.m16n8k8.row.col.f32.tf32.tf32.f32 "
        "{%0,%1,%2,%3},{%4,%5,%6,%7},{%8,%9},{%0,%1,%2,%3};"
        : "+f"(d[0]), "+f"(d[1]), "+f"(d[2]), "+f"(d[3])
        : "r"(a[0]), "r"(a[1]), "r"(a[2]), "r"(a[3]), "r"(b[0]), "r"(b[1]));
}

#define SA 20            // As row stride (16 + 4 pad) -> conflict-free frag loads
#define SB 136           // Bs row stride (128 + 8 pad)
#define ASZ (128 * SA)
#define BSZ (16 * SB)

template<int EPI, bool BT>
__global__ __launch_bounds__(128, 2)
void mma_gemm(const float* __restrict__ A,
              const float* __restrict__ B0, const float* __restrict__ B1,
              const float* __restrict__ B2,
              const float* __restrict__ Cin,
              float* __restrict__ C0, float* __restrict__ C1, float* __restrict__ C2,
              int N, int K)
{
    const float* B = (blockIdx.z == 0) ? B0 : ((blockIdx.z == 1) ? B1 : B2);
    float*       C = (blockIdx.z == 0) ? C0 : ((blockIdx.z == 1) ? C1 : C2);

    __shared__ unsigned sA[2 * ASZ];
    __shared__ unsigned sB[2 * BSZ];

    const int tid  = threadIdx.x;
    const int lane = tid & 31;
    const int warp = tid >> 5;
    const int wm = warp >> 1, wn = warp & 1;
    const int lr = lane >> 2, lq = lane & 3;
    const int rowBase = blockIdx.y * 128;
    const int colBase = blockIdx.x * 128;

    float acc[4][8][4];
    #pragma unroll
    for (int i = 0; i < 4; i++)
        #pragma unroll
        for (int j = 0; j < 8; j++)
            #pragma unroll
            for (int t = 0; t < 4; t++) acc[i][j][t] = 0.0f;

    // global staging pointers (per-thread)
    const float* aG = A + (size_t)(rowBase + (tid >> 2)) * K + (tid & 3) * 4;
    const float* bG;
    if (!BT) bG = B + (size_t)(tid >> 5) * N + colBase + (tid & 31) * 4;
    else     bG = B + (size_t)(colBase + (tid >> 2)) * K + (tid & 3) * 4;

    float4 ar[4], br[4];

    auto gload = [&](int it) {
        size_t ko = (size_t)it * 16;
        #pragma unroll
        for (int p = 0; p < 4; p++)
            ar[p] = *(const float4*)(aG + (size_t)p * 32 * K + ko);
        if (!BT) {
            #pragma unroll
            for (int p = 0; p < 4; p++)
                br[p] = *(const float4*)(bG + (size_t)(p * 4) * N + ko * N);
        } else {
            #pragma unroll
            for (int p = 0; p < 4; p++) {
                int n = colBase + (tid >> 2) + p * 32;
                br[p] = (n < N) ? *(const float4*)(bG + (size_t)p * 32 * K + ko)
                                : make_float4(0.f, 0.f, 0.f, 0.f);
            }
        }
    };

    const unsigned sAo = (tid >> 2) * SA + (tid & 3) * 4;
    auto cstore = [&](int buf) {
        unsigned* pa = sA + buf * ASZ;
        #pragma unroll
        for (int p = 0; p < 4; p++) {
            unsigned o = sAo + p * 32 * SA;
            *(uint4*)(pa + o) = make_uint4(f2tf(ar[p].x), f2tf(ar[p].y),
                                           f2tf(ar[p].z), f2tf(ar[p].w));
        }
        unsigned* pb = sB + buf * BSZ;
        if (!BT) {
            unsigned o0 = (tid >> 5) * SB + (tid & 31) * 4;
            #pragma unroll
            for (int p = 0; p < 4; p++) {
                unsigned o = o0 + p * 4 * SB;
                *(uint4*)(pb + o) = make_uint4(f2tf(br[p].x), f2tf(br[p].y),
                                               f2tf(br[p].z), f2tf(br[p].w));
            }
        } else {
            unsigned col = tid >> 2;
            unsigned kq  = (tid & 3) * 4;
            #pragma unroll
            for (int p = 0; p < 4; p++) {
                pb[(kq + 0) * SB + col + p * 32] = f2tf(br[p].x);
                pb[(kq + 1) * SB + col + p * 32] = f2tf(br[p].y);
                pb[(kq + 2) * SB + col + p * 32] = f2tf(br[p].z);
                pb[(kq + 3) * SB + col + p * 32] = f2tf(br[p].w);
            }
        }
    };

    auto compute = [&](int buf) {
        const unsigned* pa = sA + buf * ASZ;
        const unsigned* pb = sB + buf * BSZ;
        #pragma unroll
        for (int ks = 0; ks < 2; ks++) {
            int kk = ks * 8;
            unsigned af[4][4];
            #pragma unroll
            for (int mt = 0; mt < 4; mt++) {
                const unsigned* p0 = pa + (wm * 64 + mt * 16 + lr) * SA + kk + lq;
                af[mt][0] = p0[0];
                af[mt][1] = p0[8 * SA];
                af[mt][2] = p0[4];
                af[mt][3] = p0[8 * SA + 4];
            }
            unsigned bf[8][2];
            #pragma unroll
            for (int nt = 0; nt < 8; nt++) {
                const unsigned* p0 = pb + (kk + lq) * SB + wn * 64 + nt * 8 + lr;
                bf[nt][0] = p0[0];
                bf[nt][1] = p0[4 * SB];
            }
            #pragma unroll
            for (int mt = 0; mt < 4; mt++)
                #pragma unroll
                for (int nt = 0; nt < 8; nt++)
                    mma8(acc[mt][nt], af[mt], bf[nt]);
        }
    };

    const int nIter = K / 16;
    gload(0);
    cstore(0);
    __syncthreads();
    for (int it = 0; it < nIter; it++) {
        int cur = it & 1;
        if (it + 1 < nIter) gload(it + 1);
        compute(cur);
        if (it + 1 < nIter) cstore(cur ^ 1);
        __syncthreads();
    }

    // epilogue
    #pragma unroll
    for (int mt = 0; mt < 4; mt++) {
        int r0 = rowBase + wm * 64 + mt * 16 + lr;
        #pragma unroll
        for (int nt = 0; nt < 8; nt++) {
            int col = colBase + wn * 64 + nt * 8 + lq * 2;
            float* a4 = acc[mt][nt];
            float v00 = a4[0], v01 = a4[1], v10 = a4[2], v11 = a4[3];
            size_t o0 = (size_t)r0 * N + col;
            size_t o1 = (size_t)(r0 + 8) * N + col;
            if (EPI == 1) {
                float2 c0 = *(const float2*)(Cin + o0);
                float2 c1 = *(const float2*)(Cin + o1);
                v00 += c0.x; v01 += c0.y; v10 += c1.x; v11 += c1.y;
            }
            if (EPI == 2) {
                v00 = 0.5f * v00 * (1.0f + erff(v00 * 0.70710678118654752f));
                v01 = 0.5f * v01 * (1.0f + erff(v01 * 0.70710678118654752f));
                v10 = 0.5f * v10 * (1.0f + erff(v10 * 0.70710678118654752f));
                v11 = 0.5f * v11 * (1.0f + erff(v11 * 0.70710678118654752f));
            }
            if (!BT) {
                *(float2*)(C + o0) = make_float2(v00, v01);
                *(float2*)(C + o1) = make_float2(v10, v11);
            } else {
                if (col < N)     C[o0] = v00;
                if (col + 1 < N) C[o0 + 1] = v01;
                if (col < N)     C[o1] = v10;
                if (col + 1 < N) C[o1 + 1] = v11;
            }
        }
    }
}

// ---------------- attention scores ----------------
__global__ __launch_bounds__(256)
void attn_scores_kernel(const float* __restrict__ Q, const float* __restrict__ Kt,
                        float* __restrict__ S_out)
{
    int it = blockIdx.x, jt = blockIdx.y, bh = blockIdx.z;
    if (jt > it) return;
    int b = bh / HH, h = bh % HH;
    int i0 = it * 64, j0 = jt * 64;

    __shared__ float qs[64][68];
    __shared__ float ks[64][68];
    int tid = threadIdx.x;
    #pragma unroll
    for (int l = 0; l < 4; l++) {
        int idx = tid + l * 256;
        int r = idx >> 4, c4 = (idx & 15) * 4;
        *(float4*)&qs[r][c4] =
            *(const float4*)(Q + (size_t)(b * SS + i0 + r) * DD + h * DKK + c4);
        *(float4*)&ks[r][c4] =
            *(const float4*)(Kt + (size_t)(b * SS + j0 + r) * DD + h * DKK + c4);
    }
    __syncthreads();

    int ty = tid >> 4, tx = tid & 15;
    float acc[4][4] = {};
    #pragma unroll 8
    for (int k = 0; k < 64; k++) {
        float a[4], bb[4];
        #pragma unroll
        for (int ii = 0; ii < 4; ii++) a[ii] = qs[ty * 4 + ii][k];
        #pragma unroll
        for (int jj = 0; jj < 4; jj++) bb[jj] = ks[tx * 4 + jj][k];
        #pragma unroll
        for (int ii = 0; ii < 4; ii++)
            #pragma unroll
            for (int jj = 0; jj < 4; jj++)
                acc[ii][jj] = fmaf(a[ii], bb[jj], acc[ii][jj]);
    }

    const float inv_scale = 0.125f;
    #pragma unroll
    for (int ii = 0; ii < 4; ii++) {
        int i = i0 + ty * 4 + ii;
        #pragma unroll
        for (int jj = 0; jj < 4; jj++) {
            int j = j0 + tx * 4 + jj;
            float v = (j <= i) ? acc[ii][jj] * inv_scale : 0.0f;
            S_out[((size_t)bh * SS + i) * SS + j] = v;
        }
    }
}

// ---------------- causal softmax ----------------
__global__ void softmax_kernel(float* __restrict__ att)
{
    int row = blockIdx.x;
    int i   = row & (SS - 1);
    float* p = att + (size_t)row * SS;
    int n   = i + 1;
    int tid = threadIdx.x;

    __shared__ float red[256];
    float mx = -1e30f;
    for (int j = tid; j < n; j += 256) mx = fmaxf(mx, p[j]);
    red[tid] = mx; __syncthreads();
    for (int st = 128; st > 0; st >>= 1) {
        if (tid < st) red[tid] = fmaxf(red[tid], red[tid + st]);
        __syncthreads();
    }
    mx = red[0]; __syncthreads();

    float sum = 0.0f;
    for (int j = tid; j < n; j += 256) {
        float e = __expf(p[j] - mx);
        p[j] = e;
        sum += e;
    }
    red[tid] = sum; __syncthreads();
    for (int st = 128; st > 0; st >>= 1) {
        if (tid < st) red[tid] += red[tid + st];
        __syncthreads();
    }
    float inv = 1.0f / red[0];
    for (int j = tid; j < n; j += 256) p[j] *= inv;
}

// ---------------- O = att @ V ----------------
__global__ __launch_bounds__(256)
void attn_av_kernel(const float* __restrict__ att, const float* __restrict__ V,
                    float* __restrict__ O)
{
    int it = blockIdx.x, bh = blockIdx.y;
    int b = bh / HH, h = bh % HH;
    int i0 = it * 64;

    __shared__ float as_[64][68];
    __shared__ float vs [64][68];
    int tid = threadIdx.x;
    int ty = tid >> 4, tx = tid & 15;
    float acc[4][4] = {};

    const float* attBase = att + ((size_t)bh * SS + i0) * SS;
    int kmax = i0 + 64;

    for (int j0 = 0; j0 < kmax; j0 += 64) {
        #pragma unroll
        for (int l = 0; l < 4; l++) {
            int idx = tid + l * 256;
            int r = idx >> 4, c4 = (idx & 15) * 4;
            *(float4*)&as_[r][c4] = *(const float4*)(attBase + (size_t)r * SS + j0 + c4);
            *(float4*)&vs[r][c4] =
                *(const float4*)(V + (size_t)(b * SS + j0 + r) * DD + h * DKK + c4);
        }
        __syncthreads();
        #pragma unroll 8
        for (int k = 0; k < 64; k++) {
            float a[4], bb[4];
            #pragma unroll
            for (int ii = 0; ii < 4; ii++) a[ii] = as_[ty * 4 + ii][k];
            #pragma unroll
            for (int jj = 0; jj < 4; jj++) bb[jj] = vs[k][tx * 4 + jj];
            #pragma unroll
            for (int ii = 0; ii < 4; ii++)
                #pragma unroll
                for (int jj = 0; jj < 4; jj++)
                    acc[ii][jj] = fmaf(a[ii], bb[jj], acc[ii][jj]);
        }
        __syncthreads();
    }

    #pragma unroll
    for (int ii = 0; ii < 4; ii++) {
        int i = i0 + ty * 4 + ii;
        #pragma unroll
        for (int jj = 0; jj < 4; jj++) {
            int dk = tx * 4 + jj;
            O[(size_t)(b * SS + i) * DD + h * DKK + dk] = acc[ii][jj];
        }
    }
}

// ---------------- host launcher ----------------
extern "C" void kernel_launch(void* const* d_in, const int* in_sizes, int n_in,
                              void* d_out, int out_size)
{
    const int*   idx   = (const int*)  d_in[0];
    const float* wte   = (const float*)d_in[1];
    const float* wpe   = (const float*)d_in[2];
    const float* ln1_w = (const float*)d_in[3];
    const float* ln1_b = (const float*)d_in[4];
    const float* wq    = (const float*)d_in[5];
    const float* wk    = (const float*)d_in[6];
    const float* wv    = (const float*)d_in[7];
    const float* wo    = (const float*)d_in[8];
    const float* ln2_w = (const float*)d_in[9];
    const float* ln2_b = (const float*)d_in[10];
    const float* fc1   = (const float*)d_in[11];
    const float* fc2   = (const float*)d_in[12];
    const float* lnf_w = (const float*)d_in[13];
    const float* lnf_b = (const float*)d_in[14];
    float* out = (float*)d_out;

    float *x, *h, *q, *k, *v, *tmp, *ff, *att;
    cudaGetSymbolAddress((void**)&x,   g_x);
    cudaGetSymbolAddress((void**)&h,   g_h);
    cudaGetSymbolAddress((void**)&q,   g_q);
    cudaGetSymbolAddress((void**)&k,   g_k);
    cudaGetSymbolAddress((void**)&v,   g_v);
    cudaGetSymbolAddress((void**)&tmp, g_tmp);
    cudaGetSymbolAddress((void**)&ff,  g_ff);
    cudaGetSymbolAddress((void**)&att, g_att);

    embed_kernel<<<NTOK, 256>>>(idx, wte, wpe, x);

    dim3 gQKV(DD / 128, NTOK / 128, 3);   // fused q,k,v
    dim3 gD  (DD / 128, NTOK / 128, 1);
    dim3 gF  (DFF / 128, NTOK / 128, 1);

    for (int l = 0; l < LL; l++) {
        const float* Wq = wq + (size_t)l * DD * DD;
        const float* Wk = wk + (size_t)l * DD * DD;
        const float* Wv = wv + (size_t)l * DD * DD;
        const float* Wo = wo + (size_t)l * DD * DD;
        const float* W1 = fc1 + (size_t)l * DD * DFF;
        const float* W2 = fc2 + (size_t)l * DFF * DD;

        layernorm_kernel<<<NTOK, 256>>>(x, ln1_w + l * DD, ln1_b + l * DD, h);

        mma_gemm<0, false><<<gQKV, 128>>>(h, Wq, Wk, Wv, nullptr, q, k, v, DD, DD);

        attn_scores_kernel<<<dim3(SS / 64, SS / 64, BB * HH), 256>>>(q, k, att);
        softmax_kernel<<<BB * HH * SS, 256>>>(att);
        attn_av_kernel<<<dim3(SS / 64, BB * HH), 256>>>(att, v, tmp);

        mma_gemm<1, false><<<gD, 128>>>(tmp, Wo, Wo, Wo, x, x, x, x, DD, DD);

        layernorm_kernel<<<NTOK, 256>>>(x, ln2_w + l * DD, ln2_b + l * DD, h);
        mma_gemm<2, false><<<gF, 128>>>(h, W1, W1, W1, nullptr, ff, ff, ff, DFF, DD);
        mma_gemm<1, false><<<gD, 128>>>(ff, W2, W2, W2, x, x, x, x, DD, DFF);
    }

    layernorm_kernel<<<NTOK, 256>>>(x, lnf_w, lnf_b, h);
    mma_gemm<0, true><<<dim3((VV + 127) / 128, NTOK / 128, 1), 128>>>(
        h, wte, wte, wte, nullptr, out, out, out, VV, DD);
}

// round 3
// speedup vs baseline: 3.6053x; 1.4130x over previous
#include <cuda_runtime.h>
#include <cuda_bf16.h>
#include <math.h>

// ---------------- problem constants ----------------
#define BB 4
#define SS 1024
#define LL 12
#define DD 768
#define HH 12
#define DKK 64
#define DFF 3072
#define VV 50257
#define NTOK (BB*SS)          // 4096

// ---------------- scratch (device globals; no allocs allowed) --------------
__device__ float g_x  [(size_t)NTOK * DD];
__device__ float g_h  [(size_t)NTOK * DD];
__device__ float g_q  [(size_t)NTOK * DD];
__device__ float g_k  [(size_t)NTOK * DD];
__device__ float g_v  [(size_t)NTOK * DD];
__device__ float g_tmp[(size_t)NTOK * DD];
__device__ float g_ff [(size_t)NTOK * DFF];

// ---------------- embedding ----------------
__global__ void embed_kernel(const int* __restrict__ idx,
                             const float* __restrict__ wte,
                             const float* __restrict__ wpe,
                             float* __restrict__ x)
{
    int row = blockIdx.x;
    int s   = row & (SS - 1);
    int tok = idx[row];
    int tid = threadIdx.x;
    #pragma unroll
    for (int l = 0; l < 3; l++) {
        int d = tid + l * 256;
        x[(size_t)row * DD + d] = wte[(size_t)tok * DD + d] + wpe[(size_t)s * DD + d];
    }
}

// ---------------- layernorm ----------------
__global__ void layernorm_kernel(const float* __restrict__ x,
                                 const float* __restrict__ w,
                                 const float* __restrict__ b,
                                 float* __restrict__ y)
{
    int row = blockIdx.x;
    const float* p = x + (size_t)row * DD;
    int tid = threadIdx.x;
    float v0 = p[tid], v1 = p[tid + 256], v2 = p[tid + 512];
    __shared__ float red[256];
    red[tid] = v0 + v1 + v2;
    __syncthreads();
    for (int st = 128; st > 0; st >>= 1) {
        if (tid < st) red[tid] += red[tid + st];
        __syncthreads();
    }
    float mean = red[0] * (1.0f / DD);
    __syncthreads();
    float d0 = v0 - mean, d1 = v1 - mean, d2 = v2 - mean;
    red[tid] = d0 * d0 + d1 * d1 + d2 * d2;
    __syncthreads();
    for (int st = 128; st > 0; st >>= 1) {
        if (tid < st) red[tid] += red[tid + st];
        __syncthreads();
    }
    float rstd = rsqrtf(red[0] * (1.0f / DD) + 1e-5f);
    float* q = y + (size_t)row * DD;
    q[tid]       = d0 * rstd * w[tid]       + b[tid];
    q[tid + 256] = d1 * rstd * w[tid + 256] + b[tid + 256];
    q[tid + 512] = d2 * rstd * w[tid + 512] + b[tid + 512];
}

// ---------------- tf32 helpers ----------------
__device__ __forceinline__ unsigned f2tf(float f) {
    unsigned u;
    asm("cvt.rna.tf32.f32 %0, %1;" : "=r"(u) : "f"(f));
    return u;
}

__device__ __forceinline__ void mma8(float* d, const unsigned* a, const unsigned* b) {
    asm volatile(
        "mma.sync.aligned.m16n8k8.row.col.f32.tf32.tf32.f32 "
        "{%0,%1,%2,%3},{%4,%5,%6,%7},{%8,%9},{%0,%1,%2,%3};"
        : "+f"(d[0]), "+f"(d[1]), "+f"(d[2]), "+f"(d[3])
        : "r"(a[0]), "r"(a[1]), "r"(a[2]), "r"(a[3]), "r"(b[0]), "r"(b[1]));
}

// ---------------- tf32 tensor-core GEMM (as in R2) ----------------
#define SA 20
#define SB 136
#define ASZ (128 * SA)
#define BSZ (16 * SB)

template<int EPI, bool BT>
__global__ __launch_bounds__(128, 2)
void mma_gemm(const float* __restrict__ A,
              const float* __restrict__ B0, const float* __restrict__ B1,
              const float* __restrict__ B2,
              const float* __restrict__ Cin,
              float* __restrict__ C0, float* __restrict__ C1, float* __restrict__ C2,
              int N, int K)
{
    const float* B = (blockIdx.z == 0) ? B0 : ((blockIdx.z == 1) ? B1 : B2);
    float*       C = (blockIdx.z == 0) ? C0 : ((blockIdx.z == 1) ? C1 : C2);

    __shared__ unsigned sA[2 * ASZ];
    __shared__ unsigned sB[2 * BSZ];

    const int tid  = threadIdx.x;
    const int lane = tid & 31;
    const int warp = tid >> 5;
    const int wm = warp >> 1, wn = warp & 1;
    const int lr = lane >> 2, lq = lane & 3;
    const int rowBase = blockIdx.y * 128;
    const int colBase = blockIdx.x * 128;

    float acc[4][8][4];
    #pragma unroll
    for (int i = 0; i < 4; i++)
        #pragma unroll
        for (int j = 0; j < 8; j++)
            #pragma unroll
            for (int t = 0; t < 4; t++) acc[i][j][t] = 0.0f;

    const float* aG = A + (size_t)(rowBase + (tid >> 2)) * K + (tid & 3) * 4;
    const float* bG;
    if (!BT) bG = B + (size_t)(tid >> 5) * N + colBase + (tid & 31) * 4;
    else     bG = B + (size_t)(colBase + (tid >> 2)) * K + (tid & 3) * 4;

    float4 ar[4], br[4];

    auto gload = [&](int it) {
        size_t ko = (size_t)it * 16;
        #pragma unroll
        for (int p = 0; p < 4; p++)
            ar[p] = *(const float4*)(aG + (size_t)p * 32 * K + ko);
        if (!BT) {
            #pragma unroll
            for (int p = 0; p < 4; p++)
                br[p] = *(const float4*)(bG + (size_t)(p * 4) * N + ko * N);
        } else {
            #pragma unroll
            for (int p = 0; p < 4; p++) {
                int n = colBase + (tid >> 2) + p * 32;
                br[p] = (n < VV) && (n < 0x7fffffff) && (n < ((int)0x7fffffff)) && (n < ((BT)? N : N)) && (n < N)
                        ? *(const float4*)(bG + (size_t)p * 32 * K + ko)
                        : make_float4(0.f, 0.f, 0.f, 0.f);
            }
        }
    };

    const unsigned sAo = (tid >> 2) * SA + (tid & 3) * 4;
    auto cstore = [&](int buf) {
        unsigned* pa = sA + buf * ASZ;
        #pragma unroll
        for (int p = 0; p < 4; p++) {
            unsigned o = sAo + p * 32 * SA;
            *(uint4*)(pa + o) = make_uint4(f2tf(ar[p].x), f2tf(ar[p].y),
                                           f2tf(ar[p].z), f2tf(ar[p].w));
        }
        unsigned* pb = sB + buf * BSZ;
        if (!BT) {
            unsigned o0 = (tid >> 5) * SB + (tid & 31) * 4;
            #pragma unroll
            for (int p = 0; p < 4; p++) {
                unsigned o = o0 + p * 4 * SB;
                *(uint4*)(pb + o) = make_uint4(f2tf(br[p].x), f2tf(br[p].y),
                                               f2tf(br[p].z), f2tf(br[p].w));
            }
        } else {
            unsigned col = tid >> 2;
            unsigned kq  = (tid & 3) * 4;
            #pragma unroll
            for (int p = 0; p < 4; p++) {
                pb[(kq + 0) * SB + col + p * 32] = f2tf(br[p].x);
                pb[(kq + 1) * SB + col + p * 32] = f2tf(br[p].y);
                pb[(kq + 2) * SB + col + p * 32] = f2tf(br[p].z);
                pb[(kq + 3) * SB + col + p * 32] = f2tf(br[p].w);
            }
        }
    };

    auto compute = [&](int buf) {
        const unsigned* pa = sA + buf * ASZ;
        const unsigned* pb = sB + buf * BSZ;
        #pragma unroll
        for (int ks = 0; ks < 2; ks++) {
            int kk = ks * 8;
            unsigned af[4][4];
            #pragma unroll
            for (int mt = 0; mt < 4; mt++) {
                const unsigned* p0 = pa + (wm * 64 + mt * 16 + lr) * SA + kk + lq;
                af[mt][0] = p0[0];
                af[mt][1] = p0[8 * SA];
                af[mt][2] = p0[4];
                af[mt][3] = p0[8 * SA + 4];
            }
            unsigned bf[8][2];
            #pragma unroll
            for (int nt = 0; nt < 8; nt++) {
                const unsigned* p0 = pb + (kk + lq) * SB + wn * 64 + nt * 8 + lr;
                bf[nt][0] = p0[0];
                bf[nt][1] = p0[4 * SB];
            }
            #pragma unroll
            for (int mt = 0; mt < 4; mt++)
                #pragma unroll
                for (int nt = 0; nt < 8; nt++)
                    mma8(acc[mt][nt], af[mt], bf[nt]);
        }
    };

    const int nIter = K / 16;
    gload(0);
    cstore(0);
    __syncthreads();
    for (int it = 0; it < nIter; it++) {
        int cur = it & 1;
        if (it + 1 < nIter) gload(it + 1);
        compute(cur);
        if (it + 1 < nIter) cstore(cur ^ 1);
        __syncthreads();
    }

    #pragma unroll
    for (int mt = 0; mt < 4; mt++) {
        int r0 = rowBase + wm * 64 + mt * 16 + lr;
        #pragma unroll
        for (int nt = 0; nt < 8; nt++) {
            int col = colBase + wn * 64 + nt * 8 + lq * 2;
            float* a4 = acc[mt][nt];
            float v00 = a4[0], v01 = a4[1], v10 = a4[2], v11 = a4[3];
            size_t o0 = (size_t)r0 * N + col;
            size_t o1 = (size_t)(r0 + 8) * N + col;
            if (EPI == 1) {
                float2 c0 = *(const float2*)(Cin + o0);
                float2 c1 = *(const float2*)(Cin + o1);
                v00 += c0.x; v01 += c0.y; v10 += c1.x; v11 += c1.y;
            }
            if (EPI == 2) {
                v00 = 0.5f * v00 * (1.0f + erff(v00 * 0.70710678118654752f));
                v01 = 0.5f * v01 * (1.0f + erff(v01 * 0.70710678118654752f));
                v10 = 0.5f * v10 * (1.0f + erff(v10 * 0.70710678118654752f));
                v11 = 0.5f * v11 * (1.0f + erff(v11 * 0.70710678118654752f));
            }
            if (!BT) {
                *(float2*)(C + o0) = make_float2(v00, v01);
                *(float2*)(C + o1) = make_float2(v10, v11);
            } else {
                if (col < N)     C[o0] = v00;
                if (col + 1 < N) C[o0 + 1] = v01;
                if (col < N)     C[o1] = v10;
                if (col + 1 < N) C[o1 + 1] = v11;
            }
        }
    }
}

// ---------------- fused flash attention (tf32 tensor cores) ----------------
// grid (16, 48), block 128 (4 warps). Q tile 64 rows, warp = 16 rows.
// QK^T: plain tf32. P@V: compensated tf32 (P,V split hi/lo; 3 mma terms).
// smem (uint words): sQ 64*68 | sK 64*68 | sVhi 64*72 | sVlo 64*72 | sPst 4*256
#define FA_SQ   0
#define FA_SK   (64*68)
#define FA_SVH  (2*64*68)
#define FA_SVL  (2*64*68 + 64*72)
#define FA_SPST (2*64*68 + 2*64*72)
#define FA_SMEM_WORDS (2*64*68 + 2*64*72 + 4*256)

__global__ __launch_bounds__(128, 2)
void flash_attn_kernel(const float* __restrict__ Q, const float* __restrict__ K,
                       const float* __restrict__ V, float* __restrict__ O)
{
    extern __shared__ unsigned fsm[];
    unsigned* sQ  = fsm + FA_SQ;
    unsigned* sK  = fsm + FA_SK;
    unsigned* sVh = fsm + FA_SVH;
    unsigned* sVl = fsm + FA_SVL;

    const int tid  = threadIdx.x;
    const int lane = tid & 31;
    const int w    = tid >> 5;
    const int lr   = lane >> 2;
    const int lq   = lane & 3;
    const int it   = (SS / 64 - 1) - blockIdx.x;   // heavy tiles first
    const int bh   = blockIdx.y;
    const int b    = bh / HH, h = bh % HH;
    const int i0   = it * 64;

    unsigned* myP = fsm + FA_SPST + w * 256;       // [hi 128][lo 128]

    // load Q tile (64x64) as tf32
    const float* Qb = Q + (size_t)(b * SS + i0) * DD + h * DKK;
    #pragma unroll
    for (int p = 0; p < 8; p++) {
        int idx = tid + p * 128;
        int r = idx >> 4, c4 = (idx & 15) * 4;
        float4 v = *(const float4*)(Qb + (size_t)r * DD + c4);
        unsigned* d = sQ + r * 68 + c4;
        d[0] = f2tf(v.x); d[1] = f2tf(v.y); d[2] = f2tf(v.z); d[3] = f2tf(v.w);
    }

    float oacc[8][4];
    #pragma unroll
    for (int nt = 0; nt < 8; nt++)
        #pragma unroll
        for (int e = 0; e < 4; e++) oacc[nt][e] = 0.0f;
    float m0 = -1e30f, m1 = -1e30f, l0 = 0.0f, l1 = 0.0f;

    for (int j0 = 0; j0 <= i0; j0 += 64) {
        __syncthreads();   // also covers initial sQ visibility
        const float* Kb = K + (size_t)(b * SS + j0) * DD + h * DKK;
        const float* Vb = V + (size_t)(b * SS + j0) * DD + h * DKK;
        #pragma unroll
        for (int p = 0; p < 8; p++) {
            int idx = tid + p * 128;
            int r = idx >> 4, c4 = (idx & 15) * 4;
            float4 kv = *(const float4*)(Kb + (size_t)r * DD + c4);
            unsigned* dk = sK + r * 68 + c4;
            dk[0] = f2tf(kv.x); dk[1] = f2tf(kv.y); dk[2] = f2tf(kv.z); dk[3] = f2tf(kv.w);
            float4 vv = *(const float4*)(Vb + (size_t)r * DD + c4);
            unsigned* dh = sVh + r * 72 + c4;
            unsigned* dl = sVl + r * 72 + c4;
            unsigned h0 = f2tf(vv.x); dh[0] = h0; dl[0] = f2tf(vv.x - __uint_as_float(h0));
            unsigned h1 = f2tf(vv.y); dh[1] = h1; dl[1] = f2tf(vv.y - __uint_as_float(h1));
            unsigned h2 = f2tf(vv.z); dh[2] = h2; dl[2] = f2tf(vv.z - __uint_as_float(h2));
            unsigned h3 = f2tf(vv.w); dh[3] = h3; dl[3] = f2tf(vv.w - __uint_as_float(h3));
        }
        __syncthreads();

        // ---- S = Q @ K^T ----
        float sacc[8][4];
        #pragma unroll
        for (int nt = 0; nt < 8; nt++)
            #pragma unroll
            for (int e = 0; e < 4; e++) sacc[nt][e] = 0.0f;

        #pragma unroll
        for (int kk = 0; kk < 8; kk++) {
            unsigned a[4];
            const unsigned* pa = sQ + (w * 16 + lr) * 68 + kk * 8 + lq;
            a[0] = pa[0]; a[1] = pa[8 * 68]; a[2] = pa[4]; a[3] = pa[8 * 68 + 4];
            #pragma unroll
            for (int nt = 0; nt < 8; nt++) {
                unsigned bf[2];
                const unsigned* pb = sK + (nt * 8 + lr) * 68 + kk * 8 + lq;
                bf[0] = pb[0]; bf[1] = pb[4];
                mma8(sacc[nt], a, bf);
            }
        }

        // ---- scale + causal mask ----
        #pragma unroll
        for (int nt = 0; nt < 8; nt++)
            #pragma unroll
            for (int e = 0; e < 4; e++) sacc[nt][e] *= 0.125f;
        if (j0 == i0) {
            int ii0 = w * 16 + lr, ii1 = ii0 + 8;
            #pragma unroll
            for (int nt = 0; nt < 8; nt++) {
                int jj = nt * 8 + 2 * lq;
                if (jj     > ii0) sacc[nt][0] = -1e30f;
                if (jj + 1 > ii0) sacc[nt][1] = -1e30f;
                if (jj     > ii1) sacc[nt][2] = -1e30f;
                if (jj + 1 > ii1) sacc[nt][3] = -1e30f;
            }
        }

        // ---- online softmax ----
        float rm0 = -1e30f, rm1 = -1e30f;
        #pragma unroll
        for (int nt = 0; nt < 8; nt++) {
            rm0 = fmaxf(rm0, fmaxf(sacc[nt][0], sacc[nt][1]));
            rm1 = fmaxf(rm1, fmaxf(sacc[nt][2], sacc[nt][3]));
        }
        rm0 = fmaxf(rm0, __shfl_xor_sync(0xffffffffu, rm0, 1));
        rm0 = fmaxf(rm0, __shfl_xor_sync(0xffffffffu, rm0, 2));
        rm1 = fmaxf(rm1, __shfl_xor_sync(0xffffffffu, rm1, 1));
        rm1 = fmaxf(rm1, __shfl_xor_sync(0xffffffffu, rm1, 2));
        float mn0 = fmaxf(m0, rm0), mn1 = fmaxf(m1, rm1);
        float f0 = __expf(m0 - mn0), f1 = __expf(m1 - mn1);
        float ps0 = 0.0f, ps1 = 0.0f;
        #pragma unroll
        for (int nt = 0; nt < 8; nt++) {
            float p0 = __expf(sacc[nt][0] - mn0); sacc[nt][0] = p0; ps0 += p0;
            float p1 = __expf(sacc[nt][1] - mn0); sacc[nt][1] = p1; ps0 += p1;
            float p2 = __expf(sacc[nt][2] - mn1); sacc[nt][2] = p2; ps1 += p2;
            float p3 = __expf(sacc[nt][3] - mn1); sacc[nt][3] = p3; ps1 += p3;
        }
        ps0 += __shfl_xor_sync(0xffffffffu, ps0, 1);
        ps0 += __shfl_xor_sync(0xffffffffu, ps0, 2);
        ps1 += __shfl_xor_sync(0xffffffffu, ps1, 1);
        ps1 += __shfl_xor_sync(0xffffffffu, ps1, 2);
        l0 = l0 * f0 + ps0;
        l1 = l1 * f1 + ps1;
        m0 = mn0; m1 = mn1;
        #pragma unroll
        for (int nt = 0; nt < 8; nt++) {
            oacc[nt][0] *= f0; oacc[nt][1] *= f0;
            oacc[nt][2] *= f1; oacc[nt][3] *= f1;
        }

        // ---- O += P @ V (compensated tf32) ----
        #pragma unroll
        for (int kk = 0; kk < 8; kk++) {
            // stage P chunk (16x8) hi/lo via smem to get A-fragment layout
            float p0 = sacc[kk][0], p1 = sacc[kk][1], p2 = sacc[kk][2], p3 = sacc[kk][3];
            unsigned h0 = f2tf(p0), h1 = f2tf(p1), h2 = f2tf(p2), h3 = f2tf(p3);
            unsigned e0 = f2tf(p0 - __uint_as_float(h0));
            unsigned e1 = f2tf(p1 - __uint_as_float(h1));
            unsigned e2 = f2tf(p2 - __uint_as_float(h2));
            unsigned e3 = f2tf(p3 - __uint_as_float(h3));
            myP[lr * 8 + 2 * lq]             = h0;
            myP[lr * 8 + 2 * lq + 1]         = h1;
            myP[(lr + 8) * 8 + 2 * lq]       = h2;
            myP[(lr + 8) * 8 + 2 * lq + 1]   = h3;
            myP[128 + lr * 8 + 2 * lq]           = e0;
            myP[128 + lr * 8 + 2 * lq + 1]       = e1;
            myP[128 + (lr + 8) * 8 + 2 * lq]     = e2;
            myP[128 + (lr + 8) * 8 + 2 * lq + 1] = e3;
            __syncwarp();
            unsigned ah[4], al[4];
            ah[0] = myP[lr * 8 + lq];
            ah[1] = myP[(lr + 8) * 8 + lq];
            ah[2] = myP[lr * 8 + lq + 4];
            ah[3] = myP[(lr + 8) * 8 + lq + 4];
            al[0] = myP[128 + lr * 8 + lq];
            al[1] = myP[128 + (lr + 8) * 8 + lq];
            al[2] = myP[128 + lr * 8 + lq + 4];
            al[3] = myP[128 + (lr + 8) * 8 + lq + 4];
            __syncwarp();
            #pragma unroll
            for (int nt = 0; nt < 8; nt++) {
                unsigned bhv[2], blv[2];
                const unsigned* pvh = sVh + (kk * 8 + lq) * 72 + nt * 8 + lr;
                bhv[0] = pvh[0]; bhv[1] = pvh[4 * 72];
                const unsigned* pvl = sVl + (kk * 8 + lq) * 72 + nt * 8 + lr;
                blv[0] = pvl[0]; blv[1] = pvl[4 * 72];
                mma8(oacc[nt], ah, bhv);
                mma8(oacc[nt], al, bhv);
                mma8(oacc[nt], ah, blv);
            }
        }
    }

    // ---- epilogue ----
    float inv0 = 1.0f / l0, inv1 = 1.0f / l1;
    int row0 = b * SS + i0 + w * 16 + lr;
    float* Ob = O + (size_t)row0 * DD + h * DKK;
    #pragma unroll
    for (int nt = 0; nt < 8; nt++) {
        int col = nt * 8 + 2 * lq;
        *(float2*)(Ob + col) = make_float2(oacc[nt][0] * inv0, oacc[nt][1] * inv0);
        *(float2*)(Ob + (size_t)8 * DD + col) =
            make_float2(oacc[nt][2] * inv1, oacc[nt][3] * inv1);
    }
}

// ---------------- host launcher ----------------
extern "C" void kernel_launch(void* const* d_in, const int* in_sizes, int n_in,
                              void* d_out, int out_size)
{
    const int*   idx   = (const int*)  d_in[0];
    const float* wte   = (const float*)d_in[1];
    const float* wpe   = (const float*)d_in[2];
    const float* ln1_w = (const float*)d_in[3];
    const float* ln1_b = (const float*)d_in[4];
    const float* wq    = (const float*)d_in[5];
    const float* wk    = (const float*)d_in[6];
    const float* wv    = (const float*)d_in[7];
    const float* wo    = (const float*)d_in[8];
    const float* ln2_w = (const float*)d_in[9];
    const float* ln2_b = (const float*)d_in[10];
    const float* fc1   = (const float*)d_in[11];
    const float* fc2   = (const float*)d_in[12];
    const float* lnf_w = (const float*)d_in[13];
    const float* lnf_b = (const float*)d_in[14];
    float* out = (float*)d_out;

    float *x, *h, *q, *k, *v, *tmp, *ff;
    cudaGetSymbolAddress((void**)&x,   g_x);
    cudaGetSymbolAddress((void**)&h,   g_h);
    cudaGetSymbolAddress((void**)&q,   g_q);
    cudaGetSymbolAddress((void**)&k,   g_k);
    cudaGetSymbolAddress((void**)&v,   g_v);
    cudaGetSymbolAddress((void**)&tmp, g_tmp);
    cudaGetSymbolAddress((void**)&ff,  g_ff);

    const int faSmem = FA_SMEM_WORDS * 4;   // 75776 bytes
    cudaFuncSetAttribute(flash_attn_kernel,
                         cudaFuncAttributeMaxDynamicSharedMemorySize, faSmem);

    embed_kernel<<<NTOK, 256>>>(idx, wte, wpe, x);

    dim3 gQKV(DD / 128, NTOK / 128, 3);
    dim3 gD  (DD / 128, NTOK / 128, 1);
    dim3 gF  (DFF / 128, NTOK / 128, 1);

    for (int l = 0; l < LL; l++) {
        const float* Wq = wq + (size_t)l * DD * DD;
        const float* Wk = wk + (size_t)l * DD * DD;
        const float* Wv = wv + (size_t)l * DD * DD;
        const float* Wo = wo + (size_t)l * DD * DD;
        const float* W1 = fc1 + (size_t)l * DD * DFF;
        const float* W2 = fc2 + (size_t)l * DFF * DD;

        layernorm_kernel<<<NTOK, 256>>>(x, ln1_w + l * DD, ln1_b + l * DD, h);

        mma_gemm<0, false><<<gQKV, 128>>>(h, Wq, Wk, Wv, nullptr, q, k, v, DD, DD);

        flash_attn_kernel<<<dim3(SS / 64, BB * HH), 128, faSmem>>>(q, k, v, tmp);

        mma_gemm<1, false><<<gD, 128>>>(tmp, Wo, Wo, Wo, x, x, x, x, DD, DD);

        layernorm_kernel<<<NTOK, 256>>>(x, ln2_w + l * DD, ln2_b + l * DD, h);
        mma_gemm<2, false><<<gF, 128>>>(h, W1, W1, W1, nullptr, ff, ff, ff, DFF, DD);
        mma_gemm<1, false><<<gD, 128>>>(ff, W2, W2, W2, x, x, x, x, DD, DFF);
    }

    layernorm_kernel<<<NTOK, 256>>>(x, lnf_w, lnf_b, h);
    mma_gemm<0, true><<<dim3((VV + 127) / 128, NTOK / 128, 1), 128>>>(
        h, wte, wte, wte, nullptr, out, out, out, VV, DD);
}